// round 15
// baseline (speedup 1.0000x reference)
#include <cuda_runtime.h>
#include <cuda_fp16.h>
#include <math.h>
#include <stdint.h>

#define HW    4096
#define CIN   512
#define COUT  256
#define BATCH 32

// ---- proj GEMM tiling (R11-R14 known-good) ----
#define BM 128
#define BN 256
#define BK 16
#define NKT (CIN / BK)
#define NSTB 4
#define NTHREADS 512
#define NXT (HW / BN)
#define A_STRIDE_U32 260
#define B_STRIDE 268
#define A_BYTES (BM * A_STRIDE_U32 * 4)
#define B_STAGE_BYTES (BK * B_STRIDE * 4)
#define PBUF_OFF (A_BYTES + NSTB * B_STAGE_BYTES)
#define GACC_OFF (PBUF_OFF + 256 * 4)
#define SMEM_TOTAL (GACC_OFF + 512 * 4)             // 204800

// ---- attn v7: AT_L=512, 2 CTAs/SM, 4x8-row stages, lookahead-2 ----
#define AT_L 512
#define LS_STRIDE 516
#define NSTA 4
#define MSH_STRIDE 132
#define MTH_STRIDE 20
#define AT_MEMSH_OFF 0
#define AT_MEMTH_OFF (32 * MSH_STRIDE * 4)                  // 16896
#define AT_STG_OFF   (AT_MEMTH_OFF + 256 * MTH_STRIDE * 4)  // 37376
#define AT_STAGE_BYTES (8 * LS_STRIDE * 4)                  // 16512
#define AT_SMEM_TOTAL (AT_STG_OFF + NSTA * AT_STAGE_BYTES)  // 103424 -> 2 CTAs/SM

// ---------------- device scratch ----------------
__device__ float g_part[BATCH][CIN][NXT];
__device__ float g_pooled[BATCH * COUT];
__device__ float g_G[32 * 32];
__device__ float g_alpha[32 * 33];
__device__ float g_mem[BATCH * COUT];
__device__ int   g_ptr;

__device__ __forceinline__ float warp_sum(float v) {
#pragma unroll
    for (int o = 16; o; o >>= 1) v += __shfl_down_sync(0xffffffffu, v, o);
    return v;
}
__device__ __forceinline__ uint32_t smem_u32(const void* p) {
    uint32_t a;
    asm("{ .reg .u64 t; cvta.to.shared.u64 t, %1; cvt.u32.u64 %0, t; }" : "=r"(a) : "l"(p));
    return a;
}
__device__ __forceinline__ uint32_t pack_h2(float lo, float hi) {
    __half2 h = __floats2half2_rn(lo, hi);
    return *(uint32_t*)&h;
}
#define CP_ASYNC16(saddr, gaddr) \
    asm volatile("cp.async.cg.shared.global [%0], [%1], 16;" :: "r"(saddr), "l"(gaddr))
#define CP_COMMIT()   asm volatile("cp.async.commit_group;" ::: "memory")
#define CP_WAIT(n)    asm volatile("cp.async.wait_group %0;" :: "n"(n) : "memory")

#define MMA_F16(c, a, bf) \
    asm volatile("mma.sync.aligned.m16n8k16.row.col.f32.f16.f16.f32 " \
        "{%0,%1,%2,%3}, {%4,%5,%6,%7}, {%8,%9}, {%0,%1,%2,%3};" \
        : "+f"((c)[0]), "+f"((c)[1]), "+f"((c)[2]), "+f"((c)[3]) \
        : "r"((a)[0]), "r"((a)[1]), "r"((a)[2]), "r"((a)[3]), \
          "r"((bf)[0]), "r"((bf)[1]))

// ---------------- pooled v3: predsum fused (R14) ----------------
__global__ void pooled_kernel(const float* __restrict__ preds,
                              const float* __restrict__ W,
                              const float* __restrict__ bias) {
    __shared__ float gs[CIN];
    __shared__ float red[32];
    __shared__ float s_ps;
    int b = blockIdx.x;
    int t = threadIdx.x, w = t >> 5, lane = t & 31;

    const float* pr = preds + (size_t)b * HW;
    float s = pr[t] + pr[t + 1024] + pr[t + 2048] + pr[t + 3072];
    s = warp_sum(s);
    if (lane == 0) red[w] = s;
    __syncthreads();
    if (t == 0) {
        float tt = 0.f;
#pragma unroll
        for (int j = 0; j < 32; j++) tt += red[j];
        s_ps = tt;
    }

    if (t < CIN) {
        const float* pp = &g_part[b][t][0];
        float4 v0 = *(const float4*)(pp + 0);
        float4 v1 = *(const float4*)(pp + 4);
        float4 v2 = *(const float4*)(pp + 8);
        float4 v3 = *(const float4*)(pp + 12);
        gs[t] = ((v0.x + v0.y) + (v0.z + v0.w)) + ((v1.x + v1.y) + (v1.z + v1.w))
              + ((v2.x + v2.y) + (v2.z + v2.w)) + ((v3.x + v3.y) + (v3.z + v3.w));
    }
    __syncthreads();

    int o = t >> 2, q = t & 3;
    const float* wr = W + (size_t)o * CIN + q;
    float sum = 0.f;
#pragma unroll 16
    for (int j = 0; j < 128; j++) sum += wr[4 * j] * gs[q + 4 * j];
#pragma unroll
    for (int sh = 2; sh; sh >>= 1) sum += __shfl_down_sync(0xffffffffu, sum, sh, 4);
    if (q == 0)
        g_pooled[b * COUT + o] = (sum + bias[o] * s_ps) * (1.0f / (float)HW);
}

// ---------------- gram (R13) ----------------
__global__ void gram_kernel() {
    __shared__ float xs[256];
    int i = blockIdx.x;
    int t = threadIdx.x, w = t >> 5, lane = t & 31;
    xs[t] = g_pooled[i * 256 + t];
    __syncthreads();
#pragma unroll
    for (int jj = 0; jj < 4; jj++) {
        int j = w * 4 + jj;
        const float* xj = &g_pooled[j * 256];
        float s = 0.f;
#pragma unroll
        for (int k = 0; k < 8; k++) s += xs[lane + 32 * k] * xj[lane + 32 * k];
        s = warp_sum(s);
        if (lane == 0) g_G[i * 32 + j] = s;
    }
}

// ---------------- scan v3: incremental dot table -------------------------
__global__ void scan_kernel(const int* __restrict__ epoch_p) {
    __shared__ float Gs[32 * 33];
    __shared__ float SD[32 * 33];   // SD[p][j] = alpha_p . G[:, j]
    int p = threadIdx.x;            // 32 threads
    float threshold = ((float)(*epoch_p) / 10.0f - 2.0f) * 0.4f / 13.0f + 0.3f;

    for (int j = 0; j < 32; j++) Gs[j * 33 + p] = g_G[j * 32 + p];
    __syncwarp();

    float al[32];
#pragma unroll
    for (int j = 0; j < 32; j++) al[j] = 0.f;
    float m2 = 0.f;
    int ptr = 0;

    for (int i = 0; i < 32; i++) {
        float Gii = Gs[i * 33 + i];
        float dot = (p < ptr) ? SD[p * 33 + i] : 0.f;   // own row, 1 LDS
        float rm  = (m2 == 0.f) ? 1.0f : rsqrtf(m2);
        float sim = (p < ptr) ? dot * rm * rsqrtf(Gii) : -INFINITY;

        float bv = sim; int bi = p;
#pragma unroll
        for (int o = 16; o; o >>= 1) {
            float ov = __shfl_xor_sync(0xffffffffu, bv, o);
            int   oi = __shfl_xor_sync(0xffffffffu, bi, o);
            if (ov > bv || (ov == bv && oi < bi)) { bv = ov; bi = oi; }
        }
        int ema = (ptr > 0) && (bv >= threshold);
        int idx = ema ? bi : ptr;

        __syncwarp();   // all sim reads done before SD row update
        // rank-1 SD update: lane p handles column p of row idx
        float gval = Gs[i * 33 + p];
        if (ema) SD[idx * 33 + p] = SD[idx * 33 + p] * 0.9f + 0.1f * gval;
        else     SD[idx * 33 + p] = gval;

        if (p == idx) {
            if (ema) {
#pragma unroll
                for (int j = 0; j < 32; j++)
                    al[j] = al[j] * 0.9f + ((j == i) ? 0.1f : 0.f);
                m2 = 0.81f * m2 + 0.18f * dot + 0.01f * Gii;
            } else {
#pragma unroll
                for (int j = 0; j < 32; j++) al[j] = (j == i) ? 1.f : 0.f;
                m2 = Gii;
            }
        }
        if (!ema) ptr++;
        __syncwarp();
    }
#pragma unroll
    for (int j = 0; j < 32; j++) g_alpha[p * 33 + j] = al[j];
    if (p == 0) g_ptr = ptr;
}

// ---------------- recon (R13) ----------------
__global__ void recon_kernel() {
    __shared__ float als[32];
    int p = blockIdx.x;
    int t = threadIdx.x;
    if (t < 32) als[t] = g_alpha[p * 33 + t];
    __syncthreads();
    if (p >= g_ptr) return;
    float v = 0.f;
#pragma unroll
    for (int j = 0; j < 32; j++) v += als[j] * g_pooled[j * 256 + t];
    g_mem[p * 256 + t] = v;
}

// ---------------- proj GEMM (R11-R14 known-good, unchanged) --------------
__global__ __launch_bounds__(NTHREADS, 1)
void proj_mma(const float* __restrict__ feats,
              const float* __restrict__ preds,
              const float* __restrict__ W,
              const float* __restrict__ bias,
              float* __restrict__ out) {
    extern __shared__ char smem[];
    uint32_t* Au  = (uint32_t*)smem;
    float* Bs     = (float*)(smem + A_BYTES);
    float* pbuf   = (float*)(smem + PBUF_OFF);
    float* gacc   = (float*)(smem + GACC_OFF);

    int t = threadIdx.x, wid = t >> 5, lane = t & 31;
    int g = lane >> 2, tg = lane & 3;
    int b  = blockIdx.z;
    int m0 = blockIdx.y * BM;
    int n0 = blockIdx.x * BN;
    int warp_m = (wid >> 2) * 32;
    int warp_n = (wid & 3) * 64;
    bool do_g = (blockIdx.y == 0);

    const float* fb = feats + (size_t)b * CIN * HW + n0;
    uint32_t sB = smem_u32(Bs);

    if (do_g && t < 256) pbuf[t] = preds[(size_t)b * HW + n0 + t];

#pragma unroll
    for (int i = 0; i < 32; i++) {
        int c = t + i * NTHREADS;
        int row = c >> 7, col4 = (c & 127) * 4;
        float4 v = *(const float4*)(W + (size_t)(m0 + row) * CIN + col4);
        uint2 u;
        u.x = pack_h2(v.x, v.y);
        u.y = pack_h2(v.z, v.w);
        *(uint2*)(Au + row * A_STRIDE_U32 + (c & 127) * 2) = u;
    }

#pragma unroll
    for (int s = 0; s < NSTB - 1; s++) {
#pragma unroll
        for (int i = 0; i < 2; i++) {
            int c = t + i * NTHREADS;
            int row = c >> 6, col16 = c & 63;
            CP_ASYNC16(sB + s * B_STAGE_BYTES + row * (B_STRIDE * 4) + col16 * 16,
                       fb + (size_t)(s * BK + row) * HW + col16 * 4);
        }
        CP_COMMIT();
    }

    float acc[2][8][4];
#pragma unroll
    for (int mt = 0; mt < 2; mt++)
#pragma unroll
        for (int nt = 0; nt < 8; nt++)
#pragma unroll
            for (int q = 0; q < 4; q++) acc[mt][nt][q] = 0.f;

    for (int kt = 0; kt < NKT; kt++) {
        CP_WAIT(2);
        __syncthreads();
        if (kt + NSTB - 1 < NKT) {
            int s = (kt + NSTB - 1) & (NSTB - 1);
#pragma unroll
            for (int i = 0; i < 2; i++) {
                int c = t + i * NTHREADS;
                int row = c >> 6, col16 = c & 63;
                CP_ASYNC16(sB + s * B_STAGE_BYTES + row * (B_STRIDE * 4) + col16 * 16,
                           fb + (size_t)((kt + NSTB - 1) * BK + row) * HW + col16 * 4);
            }
        }
        CP_COMMIT();

        const float* BsS = Bs + (kt & (NSTB - 1)) * (BK * B_STRIDE);

        if (do_g && t < 256) {
            int kk = t >> 4, seg = t & 15;
            float s = 0.f;
#pragma unroll
            for (int j = 0; j < 16; j++)
                s += BsS[kk * B_STRIDE + seg + 16 * j] * pbuf[seg + 16 * j];
#pragma unroll
            for (int o = 8; o; o >>= 1) s += __shfl_down_sync(0xffffffffu, s, o, 16);
            if (seg == 0) gacc[kt * 16 + kk] = s;
        }

        uint32_t af[2][4];
#pragma unroll
        for (int mt = 0; mt < 2; mt++) {
            const uint32_t* ap = Au + (size_t)(warp_m + mt * 16 + g) * A_STRIDE_U32
                                 + kt * 8 + tg;
            af[mt][0] = ap[0];
            af[mt][1] = ap[8 * A_STRIDE_U32];
            af[mt][2] = ap[4];
            af[mt][3] = ap[8 * A_STRIDE_U32 + 4];
        }
        uint32_t bf[8][2];
        {
            const float* bk0 = BsS + (2 * tg) * B_STRIDE;
#pragma unroll
            for (int nt = 0; nt < 8; nt++) {
                int n = warp_n + nt * 8 + g;
                bf[nt][0] = pack_h2(bk0[n],                 bk0[B_STRIDE + n]);
                bf[nt][1] = pack_h2(bk0[8 * B_STRIDE + n],  bk0[9 * B_STRIDE + n]);
            }
        }
#pragma unroll
        for (int mt = 0; mt < 2; mt++)
#pragma unroll
            for (int nt = 0; nt < 8; nt++)
                MMA_F16(acc[mt][nt], af[mt], bf[nt]);
    }
    __syncthreads();

    if (do_g && t < 256) {
        g_part[b][t][blockIdx.x]       = gacc[t];
        g_part[b][t + 256][blockIdx.x] = gacc[t + 256];
    }

#pragma unroll
    for (int mt = 0; mt < 2; mt++) {
        int m = m0 + warp_m + mt * 16 + g;
        float bv0 = bias[m], bv1 = bias[m + 8];
        float* rowp = out + ((size_t)b * (2 * COUT) + m) * HW + n0 + warp_n + 2 * tg;
#pragma unroll
        for (int nt = 0; nt < 8; nt++) {
            *(float2*)(rowp + nt * 8)          = make_float2(acc[mt][nt][0] + bv0, acc[mt][nt][1] + bv0);
            *(float2*)(rowp + nt * 8 + 8 * HW) = make_float2(acc[mt][nt][2] + bv1, acc[mt][nt][3] + bv1);
        }
    }
}

// ---------------- attention v7: AT_L=512, 2 CTAs/SM ----------------------
__global__ __launch_bounds__(256, 2)
void attn_mma(float* __restrict__ out) {
    extern __shared__ char smc[];
    uint32_t* memSh = (uint32_t*)(smc + AT_MEMSH_OFF);  // [32][132] c-pairs
    uint32_t* memTh = (uint32_t*)(smc + AT_MEMTH_OFF);  // [256][20] p-pairs
    float* stg = (float*)(smc + AT_STG_OFF);            // 4 x [8][516]
    float* lsm = stg;                                   // [32][516] overlay

    int t = threadIdx.x, wid = t >> 5, lane = t & 31;
    int g = lane >> 2, tg = lane & 3;
    int b = blockIdx.y, l0 = blockIdx.x * AT_L;
    int ptr = g_ptr;

    for (int idx = t; idx < 32 * 128; idx += 256) {
        int p = idx >> 7, cp = idx & 127;
        uint32_t v = 0;
        if (p < ptr) v = pack_h2(g_mem[p * 256 + 2 * cp], g_mem[p * 256 + 2 * cp + 1]);
        memSh[p * MSH_STRIDE + cp] = v;
    }
    for (int idx = t; idx < 256 * 16; idx += 256) {
        int c = idx & 255, pp = idx >> 8;
        float lo = (2 * pp     < ptr) ? g_mem[(2 * pp) * 256 + c]     : 0.f;
        float hi = (2 * pp + 1 < ptr) ? g_mem[(2 * pp + 1) * 256 + c] : 0.f;
        memTh[c * MTH_STRIDE + pp] = pack_h2(lo, hi);
    }

    const float* proj = out + (size_t)b * (2 * COUT) * HW;
    float* aug = out + (size_t)b * (2 * COUT) * HW + (size_t)COUT * HW + l0;
    uint32_t sStg = smem_u32(stg);

    // stage ss = 8 c-rows; 1024 16B-chunks per stage
#define AT_LOAD(buf, ss) do {                                                  \
    _Pragma("unroll")                                                          \
    for (int i = 0; i < 4; i++) {                                              \
        int c = t + i * 256;                                                   \
        int r = c >> 7, c16 = c & 127;                                         \
        CP_ASYNC16(sStg + (buf) * AT_STAGE_BYTES + r * (LS_STRIDE * 4) + c16 * 16, \
                   proj + (size_t)((ss) * 8 + r) * HW + l0 + c16 * 4);         \
    } } while (0)

    AT_LOAD(0, 0); CP_COMMIT();
    AT_LOAD(1, 1); CP_COMMIT();

    // ---- phase 1: logit[p][l], warp covers 64 l-cols ----
    float accl[2][8][4];
#pragma unroll
    for (int mt = 0; mt < 2; mt++)
#pragma unroll
        for (int nt = 0; nt < 8; nt++)
#pragma unroll
            for (int q = 0; q < 4; q++) accl[mt][nt][q] = 0.f;
    int n0w = wid * 64;

    for (int s = 0; s < 32; s++) {
        CP_WAIT(1);
        __syncthreads();
        if (s + 2 < 32) AT_LOAD((s + 2) & 3, s + 2);
        CP_COMMIT();

        if (s & 1) {
            int kt = s >> 1;
            uint32_t af[2][4];
#pragma unroll
            for (int mt = 0; mt < 2; mt++) {
                const uint32_t* ap = memSh + (mt * 16 + g) * MSH_STRIDE + kt * 8 + tg;
                af[mt][0] = ap[0];
                af[mt][1] = ap[8 * MSH_STRIDE];
                af[mt][2] = ap[4];
                af[mt][3] = ap[8 * MSH_STRIDE + 4];
            }
            const float* a0 = stg + ((s - 1) & 3) * (8 * LS_STRIDE) + (2 * tg) * LS_STRIDE;
            const float* b0 = stg + (s & 3) * (8 * LS_STRIDE) + (2 * tg) * LS_STRIDE;
#pragma unroll
            for (int nt = 0; nt < 8; nt++) {
                int n = n0w + nt * 8 + g;
                uint32_t bf[2];
                bf[0] = pack_h2(a0[n], a0[LS_STRIDE + n]);
                bf[1] = pack_h2(b0[n], b0[LS_STRIDE + n]);
                MMA_F16(accl[0][nt], af[0], bf);
                MMA_F16(accl[1][nt], af[1], bf);
            }
        }
    }
    __syncthreads();   // all stage reads done; lsm overlay safe
#pragma unroll
    for (int mt = 0; mt < 2; mt++)
#pragma unroll
        for (int nt = 0; nt < 8; nt++) {
            int p = mt * 16 + g;
            int l = n0w + nt * 8 + 2 * tg;
            *(float2*)&lsm[p * LS_STRIDE + l]       = make_float2(accl[mt][nt][0], accl[mt][nt][1]);
            *(float2*)&lsm[(p + 8) * LS_STRIDE + l] = make_float2(accl[mt][nt][2], accl[mt][nt][3]);
        }
    __syncthreads();

    // ---- phase 2: softmax; 256 threads x 2 cols ----
#pragma unroll
    for (int cc = 0; cc < 2; cc++) {
        int col = cc * 256 + t;
        float mx = -INFINITY;
        for (int p = 0; p < ptr; p++) mx = fmaxf(mx, lsm[p * LS_STRIDE + col]);
        float ss = 0.f;
        for (int p = 0; p < ptr; p++) {
            float e = expf(lsm[p * LS_STRIDE + col] - mx);
            lsm[p * LS_STRIDE + col] = e;
            ss += e;
        }
        float inv = 1.0f / ss;
        for (int p = 0; p < ptr; p++) lsm[p * LS_STRIDE + col] *= inv;
        for (int p = ptr; p < 32; p++) lsm[p * LS_STRIDE + col] = 0.f;
    }
    __syncthreads();

    // ---- phase 3: aug = mem^T @ attn ----
    int m0w = wid * 32;
#pragma unroll
    for (int nh = 0; nh < 8; nh++) {
        float acca[2][8][4];
#pragma unroll
        for (int mt = 0; mt < 2; mt++)
#pragma unroll
            for (int nt = 0; nt < 8; nt++)
#pragma unroll
                for (int q = 0; q < 4; q++) acca[mt][nt][q] = 0.f;
#pragma unroll
        for (int ks = 0; ks < 2; ks++) {
            uint32_t af[2][4];
#pragma unroll
            for (int mt = 0; mt < 2; mt++) {
                const uint32_t* ap = memTh + (m0w + mt * 16 + g) * MTH_STRIDE + ks * 8 + tg;
                af[mt][0] = ap[0];
                af[mt][1] = ap[8 * MTH_STRIDE];
                af[mt][2] = ap[4];
                af[mt][3] = ap[8 * MTH_STRIDE + 4];
            }
            const float* bk0 = lsm + (ks * 16 + 2 * tg) * LS_STRIDE;
            uint32_t bf[8][2];
#pragma unroll
            for (int nt = 0; nt < 8; nt++) {
                int n = nh * 64 + nt * 8 + g;
                bf[nt][0] = pack_h2(bk0[n],                  bk0[LS_STRIDE + n]);
                bf[nt][1] = pack_h2(bk0[8 * LS_STRIDE + n],  bk0[9 * LS_STRIDE + n]);
            }
#pragma unroll
            for (int mt = 0; mt < 2; mt++)
#pragma unroll
                for (int nt = 0; nt < 8; nt++)
                    MMA_F16(acca[mt][nt], af[mt], bf[nt]);
        }
#pragma unroll
        for (int mt = 0; mt < 2; mt++) {
            int c = m0w + mt * 16 + g;
            float* r0 = aug + (size_t)c * HW + nh * 64 + 2 * tg;
            float* r1 = r0 + (size_t)8 * HW;
#pragma unroll
            for (int nt = 0; nt < 8; nt++) {
                *(float2*)(r0 + nt * 8) = make_float2(acca[mt][nt][0], acca[mt][nt][1]);
                *(float2*)(r1 + nt * 8) = make_float2(acca[mt][nt][2], acca[mt][nt][3]);
            }
        }
    }
#undef AT_LOAD
}

// ---------------- launch --------------------------------------------------
extern "C" void kernel_launch(void* const* d_in, const int* in_sizes, int n_in,
                              void* d_out, int out_size) {
    const float* feats = (const float*)d_in[0];
    const float* preds = (const float*)d_in[1];
    const float* W     = (const float*)d_in[2];
    const float* bias  = (const float*)d_in[3];
    const int*   epoch = (const int*)d_in[4];
    float* out = (float*)d_out;

    cudaFuncSetAttribute(proj_mma, cudaFuncAttributeMaxDynamicSharedMemorySize, SMEM_TOTAL);
    cudaFuncSetAttribute(attn_mma, cudaFuncAttributeMaxDynamicSharedMemorySize, AT_SMEM_TOTAL);

    proj_mma<<<dim3(NXT, COUT / BM, BATCH), NTHREADS, SMEM_TOTAL>>>(feats, preds, W, bias, out);
    pooled_kernel<<<BATCH, 1024>>>(preds, W, bias);
    gram_kernel<<<32, 256>>>();
    scan_kernel<<<1, 32>>>(epoch);
    recon_kernel<<<32, 256>>>();
    attn_mma<<<dim3(HW / AT_L, BATCH), 256, AT_SMEM_TOTAL>>>(out);
}